// round 16
// baseline (speedup 1.0000x reference)
#include <cuda_runtime.h>
#include <cuda_fp16.h>
#include <math.h>
#include <cstdint>

// ---------------- problem constants ----------------
#define Bsz   4
#define NTOK  13125
#define MTOT  (Bsz*NTOK)      // 52500
#define Dm    256
#define NHd   8
#define DHd   32
#define FFd   1024
#define NQC   384             // fused q-proj width: 192 off | 96 attn | 2 ref | 94 pad

__device__ __constant__ int    c_lvlH[3] = {100, 50, 25};
__device__ __constant__ int    c_lvlW[3] = {100, 50, 25};
__device__ __constant__ int    c_lvlN[3] = {10000, 2500, 625};
__device__ __constant__ size_t c_lvlOff[3] = {0, (size_t)Bsz*10000*Dm,
                                              (size_t)Bsz*10000*Dm + (size_t)Bsz*2500*Dm};

// ---------------- scratch (__device__ globals; no allocations) ----------------
__device__ __align__(16) __half g_valin [(size_t)MTOT*Dm];
__device__ __align__(16) __half g_valh  [(size_t)MTOT*Dm];
__device__ __align__(16) __half g_qh    [(size_t)MTOT*Dm];
__device__ __align__(16) float  g_qcat  [(size_t)MTOT*NQC];
__device__ __align__(16) __half g_sah   [(size_t)MTOT*Dm];
__device__ __align__(16) float  g_q     [(size_t)MTOT*Dm];
__device__ __align__(16) __half g_qnh   [(size_t)MTOT*Dm];
__device__ __align__(16) __half g_h1h   [(size_t)MTOT*FFd];

__device__ __align__(16) __half g_WvT [Dm*Dm];
__device__ __align__(16) __half g_WqT [NQC*Dm];
__device__ __align__(16) __half g_WoT [Dm*Dm];
__device__ __align__(16) __half g_W1T [FFd*Dm];
__device__ __align__(16) __half g_W2T [Dm*FFd];
__device__ float  g_bq[NQC];

// ---------------- baseline-PTX primitives ----------------
__device__ __forceinline__ uint32_t smem_u32(const void* p) {
    uint32_t a;
    asm("{ .reg .u64 t; cvta.to.shared.u64 t, %1; cvt.u32.u64 %0, t; }" : "=r"(a) : "l"(p));
    return a;
}
__device__ __forceinline__ void cpa16(uint32_t dst, const void* src, int srcBytes) {
    asm volatile("cp.async.cg.shared.global [%0], [%1], 16, %2;"
                 :: "r"(dst), "l"(src), "r"(srcBytes) : "memory");
}
__device__ __forceinline__ void cpa_commit() {
    asm volatile("cp.async.commit_group;" ::: "memory");
}
template<int N> __device__ __forceinline__ void cpa_wait() {
    asm volatile("cp.async.wait_group %0;" :: "n"(N) : "memory");
}
__device__ __forceinline__ void ldm_x4(uint32_t& r0, uint32_t& r1, uint32_t& r2, uint32_t& r3,
                                       uint32_t addr) {
    asm volatile("ldmatrix.sync.aligned.m8n8.x4.shared.b16 {%0,%1,%2,%3}, [%4];"
                 : "=r"(r0), "=r"(r1), "=r"(r2), "=r"(r3) : "r"(addr));
}
__device__ __forceinline__ void mma_f16(float* d, const uint32_t* a, uint32_t b0, uint32_t b1) {
    asm volatile(
        "mma.sync.aligned.m16n8k16.row.col.f32.f16.f16.f32 "
        "{%0,%1,%2,%3}, {%4,%5,%6,%7}, {%8,%9}, {%0,%1,%2,%3};"
        : "+f"(d[0]), "+f"(d[1]), "+f"(d[2]), "+f"(d[3])
        : "r"(a[0]), "r"(a[1]), "r"(a[2]), "r"(a[3]), "r"(b0), "r"(b1));
}
__device__ __forceinline__ uint32_t pack_h2(float a, float b) {
    __half h0 = __float2half_rn(a), h1 = __float2half_rn(b);
    return ((uint32_t)__half_as_ushort(h1) << 16) | __half_as_ushort(h0);
}

// ---------------- GEMM (wide): CTA 128(M) x 256(N), BK=32, 512 threads ------
// EPI=1: exact GELU -> fp16 Ch. EPI=2: bias -> fp16 Ch.
// EPI=3: residual + LayerNorm fused (gridDim.x==1, N==256).
#define ROWB   80
#define TILEA  (128*ROWB)               // 10240 B
#define TILEBB (256*ROWB)               // 20480 B
#define STAGEB (TILEA+TILEBB)           // 30720 B
#define NSTG   4
#define GSMEM  (NSTG*STAGEB)            // 122880 B

__device__ __forceinline__ void load_stage_w(
    int stage,
    const __half* __restrict__ A, const __half* __restrict__ B,
    int bm, int bn, int M, int K, int k0, int tid, uint32_t sb)
{
#pragma unroll
    for (int i = 0; i < 3; i++) {
        const int c   = i * 512 + tid;
        const bool isA = c < 512;
        const int cc  = isA ? c : c - 512;
        const int r   = cc >> 2;
        const int kc  = cc & 3;
        const __half* src = isA ? A : B;
        int grow = (isA ? bm : bn) + r;
        int ok = 16;
        if (isA && grow >= M) { grow = 0; ok = 0; }
        const uint32_t dst = sb + stage * STAGEB + (isA ? 0 : TILEA) + r * ROWB + kc * 16;
        cpa16(dst, src + (size_t)grow * K + k0 + kc * 8, ok);
    }
}

template<int EPI>
__global__ __launch_bounds__(512, 1)
void mma_gemm(const __half* __restrict__ A, const __half* __restrict__ B,
              const float* __restrict__ bias,
              float* __restrict__ outF, __half* __restrict__ Ch,
              const float* __restrict__ resid,
              const float* __restrict__ gamma, const float* __restrict__ beta,
              int M, int K, int N)
{
    extern __shared__ char smem[];
    const uint32_t sb = smem_u32(smem);
    const int tid = threadIdx.x, wid = tid >> 5, lane = tid & 31;
    const int bm = blockIdx.y * 128, bn = blockIdx.x * 256;
    const int wm = wid & 1, wn = wid >> 1;
    const int KT = K >> 5;

    float acc[4][4][4];
#pragma unroll
    for (int a = 0; a < 4; a++)
#pragma unroll
        for (int b = 0; b < 4; b++)
#pragma unroll
            for (int r = 0; r < 4; r++) acc[a][b][r] = 0.f;

    load_stage_w(0, A, B, bm, bn, M, K, 0,  tid, sb); cpa_commit();
    load_stage_w(1, A, B, bm, bn, M, K, 32, tid, sb); cpa_commit();
    load_stage_w(2, A, B, bm, bn, M, K, 64, tid, sb); cpa_commit();

    const int lr = lane & 15, lc = lane >> 4;

    for (int kt = 0; kt < KT; kt++) {
        cpa_wait<2>();
        __syncthreads();
        if (kt + 3 < KT)
            load_stage_w((kt + 3) % NSTG, A, B, bm, bn, M, K, (kt + 3) * 32, tid, sb);
        cpa_commit();

        const uint32_t st = sb + (kt % NSTG) * STAGEB;
#pragma unroll
        for (int kk = 0; kk < 2; kk++) {
            const uint32_t colo = kk * 32 + lc * 16;
            uint32_t ah[4][4], bh[2][4];
#pragma unroll
            for (int mi = 0; mi < 4; mi++) {
                const uint32_t ra = (wm * 64 + mi * 16 + lr) * ROWB + colo;
                ldm_x4(ah[mi][0], ah[mi][1], ah[mi][2], ah[mi][3], st + ra);
            }
#pragma unroll
            for (int ni = 0; ni < 2; ni++) {
                const uint32_t rb = (wn * 32 + ni * 16 + lr) * ROWB + colo;
                ldm_x4(bh[ni][0], bh[ni][1], bh[ni][2], bh[ni][3], st + TILEA + rb);
            }
#pragma unroll
            for (int mi = 0; mi < 4; mi++)
#pragma unroll
                for (int n = 0; n < 4; n++) {
                    const int ni = n >> 1, s = n & 1;
                    mma_f16(acc[mi][n], ah[mi], bh[ni][s], bh[ni][s + 2]);
                }
        }
    }

    const int g = lane >> 2, t2 = (lane & 3) * 2, t = lane & 3;

    if (EPI == 1 || EPI == 2) {
#pragma unroll
        for (int mi = 0; mi < 4; mi++) {
            const int r0 = bm + wm * 64 + mi * 16 + g;
#pragma unroll
            for (int n = 0; n < 4; n++) {
                const int col = bn + wn * 32 + n * 8 + t2;
                const float b0 = bias[col], b1 = bias[col + 1];
#pragma unroll
                for (int h = 0; h < 2; h++) {
                    const int row = r0 + h * 8;
                    if (row >= M) continue;
                    float v0 = acc[mi][n][2 * h + 0] + b0;
                    float v1 = acc[mi][n][2 * h + 1] + b1;
                    if (EPI == 1) {
                        v0 = 0.5f * v0 * (1.f + erff(v0 * 0.70710678118654752f));
                        v1 = 0.5f * v1 * (1.f + erff(v1 * 0.70710678118654752f));
                    }
                    *(uint32_t*)(Ch + (size_t)row * N + col) = pack_h2(v0, v1);
                }
            }
        }
    } else {   // EPI == 3: fused residual + LayerNorm
        __syncthreads();
        float* sred = (float*)smem;
#pragma unroll
        for (int mi = 0; mi < 4; mi++) {
#pragma unroll
            for (int h = 0; h < 2; h++) {
                const int rl = wm * 64 + mi * 16 + g + h * 8;
                const int grow = bm + rl;
                const int gr = (grow < M) ? grow : 0;
                float ps = 0.f, pq = 0.f;
#pragma unroll
                for (int n = 0; n < 4; n++) {
                    const int col = wn * 32 + n * 8 + t2;
                    const float2 qv = *(const float2*)(resid + (size_t)gr * 256 + col);
                    const float v0 = acc[mi][n][2 * h + 0] + bias[col] + qv.x;
                    const float v1 = acc[mi][n][2 * h + 1] + bias[col + 1] + qv.y;
                    acc[mi][n][2 * h + 0] = v0;
                    acc[mi][n][2 * h + 1] = v1;
                    ps += v0 + v1;
                    pq += v0 * v0 + v1 * v1;
                }
                ps += __shfl_xor_sync(0xffffffffu, ps, 1);
                pq += __shfl_xor_sync(0xffffffffu, pq, 1);
                ps += __shfl_xor_sync(0xffffffffu, ps, 2);
                pq += __shfl_xor_sync(0xffffffffu, pq, 2);
                if (t == 0) {
                    sred[rl * 8 + wn] = ps;
                    sred[1024 + rl * 8 + wn] = pq;
                }
            }
        }
        __syncthreads();
#pragma unroll
        for (int mi = 0; mi < 4; mi++) {
#pragma unroll
            for (int h = 0; h < 2; h++) {
                const int rl = wm * 64 + mi * 16 + g + h * 8;
                const int grow = bm + rl;
                if (grow >= M) continue;
                float ts = 0.f, tq = 0.f;
#pragma unroll
                for (int i = 0; i < 8; i++) {
                    ts += sred[rl * 8 + i];
                    tq += sred[1024 + rl * 8 + i];
                }
                const float mean = ts * (1.f / 256.f);
                const float var  = fmaxf(tq * (1.f / 256.f) - mean * mean, 0.f);
                const float inv  = rsqrtf(var + 1e-5f);
#pragma unroll
                for (int n = 0; n < 4; n++) {
                    const int col = wn * 32 + n * 8 + t2;
                    const float o0 = (acc[mi][n][2 * h + 0] - mean) * inv * gamma[col]     + beta[col];
                    const float o1 = (acc[mi][n][2 * h + 1] - mean) * inv * gamma[col + 1] + beta[col + 1];
                    *(float2*)(outF + (size_t)grow * 256 + col) = make_float2(o0, o1);
                    if (Ch) *(uint32_t*)(Ch + (size_t)grow * 256 + col) = pack_h2(o0, o1);
                }
            }
        }
    }
}

// ---------------- GEMM (narrow): CTA 128x128, BK=32, 256 threads, fp32 out --
#define STAGEB2 (2*TILEA)
#define GSMEM2  (NSTG*STAGEB2)

__device__ __forceinline__ void load_stage_n(
    int stage,
    const __half* __restrict__ A, const __half* __restrict__ B,
    int bm, int bn, int M, int K, int k0, int tid, uint32_t sb)
{
#pragma unroll
    for (int i = 0; i < 4; i++) {
        const int c   = i * 256 + tid;
        const bool isA = c < 512;
        const int cc  = isA ? c : c - 512;
        const int r   = cc >> 2;
        const int kc  = cc & 3;
        const __half* src = isA ? A : B;
        int grow = (isA ? bm : bn) + r;
        int ok = 16;
        if (isA && grow >= M) { grow = 0; ok = 0; }
        const uint32_t dst = sb + stage * STAGEB2 + (isA ? 0 : TILEA) + r * ROWB + kc * 16;
        cpa16(dst, src + (size_t)grow * K + k0 + kc * 8, ok);
    }
}

__global__ __launch_bounds__(256, 1)
void mma_gemm_n(const __half* __restrict__ A, const __half* __restrict__ B,
                const float* __restrict__ bias, float* __restrict__ C,
                int M, int K, int N)
{
    extern __shared__ char smem[];
    const uint32_t sb = smem_u32(smem);
    const int tid = threadIdx.x, wid = tid >> 5, lane = tid & 31;
    const int bm = blockIdx.y * 128, bn = blockIdx.x * 128;
    const int wm = wid & 1, wn = wid >> 1;
    const int KT = K >> 5;

    float acc[4][4][4];
#pragma unroll
    for (int a = 0; a < 4; a++)
#pragma unroll
        for (int b = 0; b < 4; b++)
#pragma unroll
            for (int r = 0; r < 4; r++) acc[a][b][r] = 0.f;

    load_stage_n(0, A, B, bm, bn, M, K, 0,  tid, sb); cpa_commit();
    load_stage_n(1, A, B, bm, bn, M, K, 32, tid, sb); cpa_commit();
    load_stage_n(2, A, B, bm, bn, M, K, 64, tid, sb); cpa_commit();

    const int lr = lane & 15, lc = lane >> 4;

    for (int kt = 0; kt < KT; kt++) {
        cpa_wait<2>();
        __syncthreads();
        if (kt + 3 < KT)
            load_stage_n((kt + 3) % NSTG, A, B, bm, bn, M, K, (kt + 3) * 32, tid, sb);
        cpa_commit();

        const uint32_t st = sb + (kt % NSTG) * STAGEB2;
#pragma unroll
        for (int kk = 0; kk < 2; kk++) {
            const uint32_t colo = kk * 32 + lc * 16;
            uint32_t ah[4][4], bh[2][4];
#pragma unroll
            for (int mi = 0; mi < 4; mi++) {
                const uint32_t ra = (wm * 64 + mi * 16 + lr) * ROWB + colo;
                ldm_x4(ah[mi][0], ah[mi][1], ah[mi][2], ah[mi][3], st + ra);
            }
#pragma unroll
            for (int ni = 0; ni < 2; ni++) {
                const uint32_t rb = (wn * 32 + ni * 16 + lr) * ROWB + colo;
                ldm_x4(bh[ni][0], bh[ni][1], bh[ni][2], bh[ni][3], st + TILEA + rb);
            }
#pragma unroll
            for (int mi = 0; mi < 4; mi++)
#pragma unroll
                for (int n = 0; n < 4; n++) {
                    const int ni = n >> 1, s = n & 1;
                    mma_f16(acc[mi][n], ah[mi], bh[ni][s], bh[ni][s + 2]);
                }
        }
    }

    const int g = lane >> 2, t2 = (lane & 3) * 2;
#pragma unroll
    for (int mi = 0; mi < 4; mi++) {
        const int r0 = bm + wm * 64 + mi * 16 + g;
#pragma unroll
        for (int n = 0; n < 4; n++) {
            const int col = bn + wn * 32 + n * 8 + t2;
            const float b0 = bias[col], b1 = bias[col + 1];
#pragma unroll
            for (int h = 0; h < 2; h++) {
                const int row = r0 + h * 8;
                if (row >= M) continue;
                *(float2*)(C + (size_t)row * N + col) =
                    make_float2(acc[mi][n][2 * h + 0] + b0, acc[mi][n][2 * h + 1] + b1);
            }
        }
    }
}

// ---------------- fused prep: activations + weight transposes + bias -------
#define SEG0 65536
#define SEG1 (SEG0+49152)
#define SEG2 (SEG1+24576)
#define SEG3 (SEG2+512)
#define SEG4 (SEG3+24064)
#define SEG5 (SEG4+65536)
#define SEG6 (SEG5+262144)
#define SEG7 (SEG6+262144)
#define SEG8 (SEG7+384)

#define AQ4  (MTOT*Dm/4)
#define A34  (Bsz*10000*Dm/4)
#define A44  (Bsz*2500*Dm/4)
#define A54  (Bsz*625*Dm/4)
#define NA4  (AQ4+A34+A44+A54)

__global__ void prep_all(const float4* __restrict__ q,  const float4* __restrict__ p3,
                         const float4* __restrict__ p4, const float4* __restrict__ p5,
                         __half* __restrict__ qh, __half* __restrict__ valin,
                         const float* __restrict__ Wv,
                         const float* __restrict__ Woff, const float* __restrict__ Wattn,
                         const float* __restrict__ Wref, const float* __restrict__ Wo,
                         const float* __restrict__ W1,   const float* __restrict__ W2,
                         const float* __restrict__ boff, const float* __restrict__ battn,
                         const float* __restrict__ bref,
                         __half* __restrict__ WvT, __half* __restrict__ WqT,
                         __half* __restrict__ WoT, __half* __restrict__ W1T,
                         __half* __restrict__ W2T, float* __restrict__ bq)
{
    const int i = blockIdx.x * blockDim.x + threadIdx.x;
    if (i < NA4) {
        float4 v; __half* dst; int o;
        if (i < AQ4)                  { v = q [i];                   dst = qh;    o = i; }
        else if (i < AQ4 + A34)       { v = p3[i - AQ4];             dst = valin; o = i - AQ4; }
        else if (i < AQ4 + A34 + A44) { v = p4[i - AQ4 - A34];       dst = valin; o = i - AQ4; }
        else                          { v = p5[i - AQ4 - A34 - A44]; dst = valin; o = i - AQ4; }
        uint2 uh;
        uh.x = pack_h2(v.x, v.y);
        uh.y = pack_h2(v.z, v.w);
        *(uint2*)(dst + (size_t)o * 4) = uh;
        return;
    }
    const int w = i - NA4;
    if (w < SEG0) {
        const int n = w / Dm, k = w % Dm;
        WvT[w] = __float2half_rn(Wv[(size_t)k * Dm + n]);
    } else if (w < SEG1) {
        const int j = w - SEG0, n = j / Dm, k = j % Dm;
        WqT[j] = __float2half_rn(Woff[(size_t)k * 192 + n]);
    } else if (w < SEG2) {
        const int j = w - SEG1, n = j / Dm, k = j % Dm;
        WqT[192 * Dm + j] = __float2half_rn(Wattn[(size_t)k * 96 + n]);
    } else if (w < SEG3) {
        const int j = w - SEG2, n = j / Dm, k = j % Dm;
        WqT[288 * Dm + j] = __float2half_rn(Wref[(size_t)k * 2 + n]);
    } else if (w < SEG4) {
        WqT[290 * Dm + (w - SEG3)] = __float2half_rn(0.f);
    } else if (w < SEG5) {
        const int j = w - SEG4, n = j / Dm, k = j % Dm;
        WoT[j] = __float2half_rn(Wo[(size_t)k * Dm + n]);
    } else if (w < SEG6) {
        const int j = w - SEG5, n = j / Dm, k = j % Dm;
        W1T[j] = __float2half_rn(W1[(size_t)k * FFd + n]);
    } else if (w < SEG7) {
        const int j = w - SEG6, n = j / FFd, k = j % FFd;
        W2T[j] = __float2half_rn(W2[(size_t)k * Dm + n]);
    } else if (w < SEG8) {
        const int j = w - SEG7;
        bq[j] = (j < 192) ? boff[j] : (j < 288) ? battn[j - 192] : (j < 290) ? bref[j - 288] : 0.f;
    }
}

// ---------------- fused softmax + sigmoid + bilinear sampling ----------------
// 16 threads/token, 12 tokens per 192-thread block; thread = (head, 16-ch half).
// Per-point recompute; half2 accumulation held across the 4 points of each
// level (8 half2 accumulators = 16 channels), fp32 finalize per level.
#define TPB_S 192
#define TOKB  12
__global__ __launch_bounds__(TPB_S)
void sample_kernel(__half* __restrict__ oh)
{
    const int tid  = threadIdx.x;
    const int sub  = tid >> 4;                 // token in block (0..11)
    const int t    = blockIdx.x * TOKB + sub;
    const int b    = t / NTOK;
    const int tid2 = tid & 15;
    const int h    = tid2 >> 1;                // head (0..7)
    const int cw   = tid2 & 1;                 // channel half (16 ch)

    __shared__ float s_aw[TOKB][96], s_x[TOKB][96], s_y[TOKB][96];

    const float refx = 1.f / (1.f + __expf(-g_qcat[(size_t)t * NQC + 288]));
    const float refy = 1.f / (1.f + __expf(-g_qcat[(size_t)t * NQC + 289]));

    for (int i = tid2; i < 96; i += 16) {
        const int lp = i % 12;
        const int l  = lp >> 2;
        const float ox = g_qcat[(size_t)t * NQC + i * 2 + 0];
        const float oy = g_qcat[(size_t)t * NQC + i * 2 + 1];
        s_x[sub][i]  = fmaf(refx, (float)c_lvlW[l], ox) - 0.5f;
        s_y[sub][i]  = fmaf(refy, (float)c_lvlH[l], oy) - 0.5f;
        s_aw[sub][i] = g_qcat[(size_t)t * NQC + 192 + i];
    }
    __syncthreads();

    if (tid2 < 8) {    // per-head softmax over 12 (l,p)
        float m = -1e30f;
#pragma unroll
        for (int j = 0; j < 12; j++) m = fmaxf(m, s_aw[sub][tid2 * 12 + j]);
        float s = 0.f;
#pragma unroll
        for (int j = 0; j < 12; j++) {
            const float e = __expf(s_aw[sub][tid2 * 12 + j] - m);
            s_aw[sub][tid2 * 12 + j] = e; s += e;
        }
        const float inv = 1.f / s;
#pragma unroll
        for (int j = 0; j < 12; j++) s_aw[sub][tid2 * 12 + j] *= inv;
    }
    __syncthreads();

    float acc[16];
#pragma unroll
    for (int i = 0; i < 16; i++) acc[i] = 0.f;

#pragma unroll
    for (int l = 0; l < 3; l++) {
        const int Hl = c_lvlH[l], Wl = c_lvlW[l];
        const __half* vl = g_valh + c_lvlOff[l] + (size_t)b * c_lvlN[l] * Dm + (h * DHd + cw * 16);

        __half2 pa[8];
#pragma unroll
        for (int i = 0; i < 8; i++) pa[i] = __float2half2_rn(0.f);

#pragma unroll
        for (int p = 0; p < 4; p++) {
            const int idx = h * 12 + l * 4 + p;
            const float x = s_x[sub][idx], y = s_y[sub][idx], w = s_aw[sub][idx];
            const float x0f = floorf(x), y0f = floorf(y);
            const int x0 = (int)x0f, y0 = (int)y0f;
            const float lx = x - x0f, ly = y - y0f;
            const float w00 = w * (1.f - lx) * (1.f - ly);
            const float w01 = w * lx * (1.f - ly);
            const float w10 = w * (1.f - lx) * ly;
            const float w11 = w * lx * ly;
            const bool xin0 = (x0 >= 0) & (x0 < Wl);
            const bool xin1 = (x0 + 1 >= 0) & (x0 + 1 < Wl);
            const bool yin0 = (y0 >= 0) & (y0 < Hl);
            const bool yin1 = (y0 + 1 >= 0) & (y0 + 1 < Hl);
#define ACC16(cond, wgt, ro, co) \
            if (cond) { \
                const __half2 wh = __float2half2_rn(wgt); \
                const __half* cp = vl + (size_t)((ro) * Wl + (co)) * Dm; \
                const uint4 u0 = *(const uint4*)(cp); \
                const uint4 u1 = *(const uint4*)(cp + 8); \
                const __half2* h0p = (const __half2*)&u0; \
                const __half2* h1p = (const __half2*)&u1; \
                pa[0] = __hfma2(h0p[0], wh, pa[0]); \
                pa[1] = __hfma2(h0p[1], wh, pa[1]); \
                pa[2] = __hfma2(h0p[2], wh, pa[2]); \
                pa[3] = __hfma2(h0p[3], wh, pa[3]); \
                pa[4] = __hfma2(h1p[0], wh, pa[4]); \
                pa[5] = __hfma2(h1p[1], wh, pa[5]); \
                pa[6] = __hfma2(h1p[2], wh, pa[6]); \
                pa[7] = __hfma2(h1p[3], wh, pa[7]); \
            }
            ACC16(xin0 & yin0, w00, y0,     x0)
            ACC16(xin1 & yin0, w01, y0,     x0 + 1)
            ACC16(xin0 & yin1, w10, y0 + 1, x0)
            ACC16(xin1 & yin1, w11, y0 + 1, x0 + 1)
#undef ACC16
        }
        // finalize once per level
#pragma unroll
        for (int i = 0; i < 8; i++) {
            const float2 f = __half22float2(pa[i]);
            acc[2 * i + 0] += f.x;
            acc[2 * i + 1] += f.y;
        }
    }
    uint4 o0, o1;
    o0.x = pack_h2(acc[0],  acc[1]);
    o0.y = pack_h2(acc[2],  acc[3]);
    o0.z = pack_h2(acc[4],  acc[5]);
    o0.w = pack_h2(acc[6],  acc[7]);
    o1.x = pack_h2(acc[8],  acc[9]);
    o1.y = pack_h2(acc[10], acc[11]);
    o1.z = pack_h2(acc[12], acc[13]);
    o1.w = pack_h2(acc[14], acc[15]);
    __half* op = oh + (size_t)t * Dm + h * DHd + cw * 16;
    *(uint4*)(op)     = o0;
    *(uint4*)(op + 8) = o1;
}

// ---------------- host orchestration ----------------
extern "C" void kernel_launch(void* const* d_in, const int* in_sizes, int n_in,
                              void* d_out, int out_size)
{
    const float* query = (const float*)d_in[0];
    const float* p3    = (const float*)d_in[1];
    const float* p4    = (const float*)d_in[2];
    const float* p5    = (const float*)d_in[3];
    const float* Wv    = (const float*)d_in[4];
    const float* bv    = (const float*)d_in[5];
    const float* Woff  = (const float*)d_in[6];
    const float* boff  = (const float*)d_in[7];
    const float* Wattn = (const float*)d_in[8];
    const float* battn = (const float*)d_in[9];
    const float* Wref  = (const float*)d_in[10];
    const float* bref  = (const float*)d_in[11];
    const float* Wo    = (const float*)d_in[12];
    const float* bo    = (const float*)d_in[13];
    const float* W1    = (const float*)d_in[14];
    const float* b1    = (const float*)d_in[15];
    const float* W2    = (const float*)d_in[16];
    const float* b2    = (const float*)d_in[17];
    const float* g1    = (const float*)d_in[18];
    const float* be1   = (const float*)d_in[19];
    const float* g2    = (const float*)d_in[20];
    const float* be2   = (const float*)d_in[21];
    float* out = (float*)d_out;

    cudaFuncSetAttribute(mma_gemm<1>, cudaFuncAttributeMaxDynamicSharedMemorySize, GSMEM);
    cudaFuncSetAttribute(mma_gemm<2>, cudaFuncAttributeMaxDynamicSharedMemorySize, GSMEM);
    cudaFuncSetAttribute(mma_gemm<3>, cudaFuncAttributeMaxDynamicSharedMemorySize, GSMEM);
    cudaFuncSetAttribute(mma_gemm_n,  cudaFuncAttributeMaxDynamicSharedMemorySize, GSMEM2);

#define SYM(T, p, s) T* p; cudaGetSymbolAddress((void**)&p, s)
    SYM(__half, valin, g_valin);
    SYM(__half, valh, g_valh);
    SYM(__half, qh, g_qh);
    SYM(float, qcat, g_qcat);
    SYM(__half, sah, g_sah);
    SYM(float, qf, g_q);
    SYM(__half, qnh, g_qnh);
    SYM(__half, h1h, g_h1h);
    SYM(__half, WvT, g_WvT); SYM(__half, WqT, g_WqT);
    SYM(__half, WoT, g_WoT); SYM(__half, W1T, g_W1T); SYM(__half, W2T, g_W2T);
    SYM(float, bq, g_bq);
#undef SYM

    // ---- fused prep (1 launch) ----
    prep_all<<<(NA4 + SEG8 + 255) / 256, 256>>>(
        (const float4*)query, (const float4*)p3, (const float4*)p4, (const float4*)p5,
        qh, valin,
        Wv, Woff, Wattn, Wref, Wo, W1, W2, boff, battn, bref,
        WvT, WqT, WoT, W1T, W2T, bq);

    const int TM = (MTOT + 127) / 128;   // 411

    // ---- value projection (fp16 out) ----
    mma_gemm<2><<<dim3(1, TM), 512, GSMEM>>>(valin, WvT, bv, nullptr, valh,
                                             nullptr, nullptr, nullptr, MTOT, Dm, Dm);
    // ---- fused q projections (off|attn|ref, N=384, narrow tiles) ----
    mma_gemm_n<<<dim3(3, TM), 256, GSMEM2>>>(qh, WqT, bq, qcat, MTOT, Dm, NQC);
    // ---- sampling ----
    sample_kernel<<<MTOT / TOKB, TPB_S>>>(sah);
    // ---- output projection + residual + LN1 (fused) ----
    mma_gemm<3><<<dim3(1, TM), 512, GSMEM>>>(sah, WoT, bo, qf, qnh,
                                             query, g1, be1, MTOT, Dm, Dm);
    // ---- FFN ----
    mma_gemm<1><<<dim3(4, TM), 512, GSMEM>>>(qnh, W1T, b1, nullptr, h1h,
                                             nullptr, nullptr, nullptr, MTOT, Dm, FFd);
    mma_gemm<3><<<dim3(1, TM), 512, GSMEM>>>(h1h, W2T, b2, out, nullptr,
                                             qf, g2, be2, MTOT, FFd, Dm);
}

// round 17
// speedup vs baseline: 1.0783x; 1.0783x over previous
#include <cuda_runtime.h>
#include <cuda_fp16.h>
#include <math.h>
#include <cstdint>

// ---------------- problem constants ----------------
#define Bsz   4
#define NTOK  13125
#define MTOT  (Bsz*NTOK)      // 52500
#define Dm    256
#define NHd   8
#define DHd   32
#define FFd   1024
#define NQC   384             // fused q-proj width: 192 off | 96 attn | 2 ref | 94 pad
#define NQUSE 290             // used columns of qcat

__device__ __constant__ int    c_lvlH[3] = {100, 50, 25};
__device__ __constant__ int    c_lvlW[3] = {100, 50, 25};
__device__ __constant__ int    c_lvlN[3] = {10000, 2500, 625};
__device__ __constant__ size_t c_lvlOff[3] = {0, (size_t)Bsz*10000*Dm,
                                              (size_t)Bsz*10000*Dm + (size_t)Bsz*2500*Dm};

// ---------------- scratch (__device__ globals; no allocations) ----------------
__device__ __align__(16) __half g_valin [(size_t)MTOT*Dm];
__device__ __align__(16) __half g_valh  [(size_t)MTOT*Dm];
__device__ __align__(16) __half g_qh    [(size_t)MTOT*Dm];
__device__ __align__(16) float  g_qcat  [(size_t)MTOT*NQC];
__device__ __align__(16) __half g_sah   [(size_t)MTOT*Dm];
__device__ __align__(16) float  g_q     [(size_t)MTOT*Dm];
__device__ __align__(16) __half g_qnh   [(size_t)MTOT*Dm];
__device__ __align__(16) __half g_h1h   [(size_t)MTOT*FFd];

__device__ __align__(16) __half g_WvT [Dm*Dm];
__device__ __align__(16) __half g_WqT [NQC*Dm];
__device__ __align__(16) __half g_WoT [Dm*Dm];
__device__ __align__(16) __half g_W1T [FFd*Dm];
__device__ __align__(16) __half g_W2T [Dm*FFd];
__device__ float  g_bq[NQC];

// ---------------- baseline-PTX primitives ----------------
__device__ __forceinline__ uint32_t smem_u32(const void* p) {
    uint32_t a;
    asm("{ .reg .u64 t; cvta.to.shared.u64 t, %1; cvt.u32.u64 %0, t; }" : "=r"(a) : "l"(p));
    return a;
}
__device__ __forceinline__ void cpa16(uint32_t dst, const void* src, int srcBytes) {
    asm volatile("cp.async.cg.shared.global [%0], [%1], 16, %2;"
                 :: "r"(dst), "l"(src), "r"(srcBytes) : "memory");
}
__device__ __forceinline__ void cpa_commit() {
    asm volatile("cp.async.commit_group;" ::: "memory");
}
template<int N> __device__ __forceinline__ void cpa_wait() {
    asm volatile("cp.async.wait_group %0;" :: "n"(N) : "memory");
}
__device__ __forceinline__ void ldm_x4(uint32_t& r0, uint32_t& r1, uint32_t& r2, uint32_t& r3,
                                       uint32_t addr) {
    asm volatile("ldmatrix.sync.aligned.m8n8.x4.shared.b16 {%0,%1,%2,%3}, [%4];"
                 : "=r"(r0), "=r"(r1), "=r"(r2), "=r"(r3) : "r"(addr));
}
__device__ __forceinline__ void mma_f16(float* d, const uint32_t* a, uint32_t b0, uint32_t b1) {
    asm volatile(
        "mma.sync.aligned.m16n8k16.row.col.f32.f16.f16.f32 "
        "{%0,%1,%2,%3}, {%4,%5,%6,%7}, {%8,%9}, {%0,%1,%2,%3};"
        : "+f"(d[0]), "+f"(d[1]), "+f"(d[2]), "+f"(d[3])
        : "r"(a[0]), "r"(a[1]), "r"(a[2]), "r"(a[3]), "r"(b0), "r"(b1));
}
__device__ __forceinline__ uint32_t pack_h2(float a, float b) {
    __half h0 = __float2half_rn(a), h1 = __float2half_rn(b);
    return ((uint32_t)__half_as_ushort(h1) << 16) | __half_as_ushort(h0);
}

// ---------------- GEMM (wide): CTA 128(M) x 256(N), BK=32, 512 threads ------
// EPI=1: exact GELU -> fp16 Ch. EPI=2: bias -> fp16 Ch.
// EPI=3: residual + LayerNorm fused (gridDim.x==1, N==256).
#define ROWB   80
#define TILEA  (128*ROWB)               // 10240 B
#define TILEBB (256*ROWB)               // 20480 B
#define STAGEB (TILEA+TILEBB)           // 30720 B
#define NSTG   4
#define GSMEM  (NSTG*STAGEB)            // 122880 B

__device__ __forceinline__ void load_stage_w(
    int stage,
    const __half* __restrict__ A, const __half* __restrict__ B,
    int bm, int bn, int M, int K, int k0, int tid, uint32_t sb)
{
#pragma unroll
    for (int i = 0; i < 3; i++) {
        const int c   = i * 512 + tid;
        const bool isA = c < 512;
        const int cc  = isA ? c : c - 512;
        const int r   = cc >> 2;
        const int kc  = cc & 3;
        const __half* src = isA ? A : B;
        int grow = (isA ? bm : bn) + r;
        int ok = 16;
        if (isA && grow >= M) { grow = 0; ok = 0; }
        const uint32_t dst = sb + stage * STAGEB + (isA ? 0 : TILEA) + r * ROWB + kc * 16;
        cpa16(dst, src + (size_t)grow * K + k0 + kc * 8, ok);
    }
}

template<int EPI>
__global__ __launch_bounds__(512, 1)
void mma_gemm(const __half* __restrict__ A, const __half* __restrict__ B,
              const float* __restrict__ bias,
              float* __restrict__ outF, __half* __restrict__ Ch,
              const float* __restrict__ resid,
              const float* __restrict__ gamma, const float* __restrict__ beta,
              int M, int K, int N)
{
    extern __shared__ char smem[];
    const uint32_t sb = smem_u32(smem);
    const int tid = threadIdx.x, wid = tid >> 5, lane = tid & 31;
    const int bm = blockIdx.y * 128, bn = blockIdx.x * 256;
    const int wm = wid & 1, wn = wid >> 1;
    const int KT = K >> 5;

    float acc[4][4][4];
#pragma unroll
    for (int a = 0; a < 4; a++)
#pragma unroll
        for (int b = 0; b < 4; b++)
#pragma unroll
            for (int r = 0; r < 4; r++) acc[a][b][r] = 0.f;

    load_stage_w(0, A, B, bm, bn, M, K, 0,  tid, sb); cpa_commit();
    load_stage_w(1, A, B, bm, bn, M, K, 32, tid, sb); cpa_commit();
    load_stage_w(2, A, B, bm, bn, M, K, 64, tid, sb); cpa_commit();

    const int lr = lane & 15, lc = lane >> 4;

    for (int kt = 0; kt < KT; kt++) {
        cpa_wait<2>();
        __syncthreads();
        if (kt + 3 < KT)
            load_stage_w((kt + 3) % NSTG, A, B, bm, bn, M, K, (kt + 3) * 32, tid, sb);
        cpa_commit();

        const uint32_t st = sb + (kt % NSTG) * STAGEB;
#pragma unroll
        for (int kk = 0; kk < 2; kk++) {
            const uint32_t colo = kk * 32 + lc * 16;
            uint32_t ah[4][4], bh[2][4];
#pragma unroll
            for (int mi = 0; mi < 4; mi++) {
                const uint32_t ra = (wm * 64 + mi * 16 + lr) * ROWB + colo;
                ldm_x4(ah[mi][0], ah[mi][1], ah[mi][2], ah[mi][3], st + ra);
            }
#pragma unroll
            for (int ni = 0; ni < 2; ni++) {
                const uint32_t rb = (wn * 32 + ni * 16 + lr) * ROWB + colo;
                ldm_x4(bh[ni][0], bh[ni][1], bh[ni][2], bh[ni][3], st + TILEA + rb);
            }
#pragma unroll
            for (int mi = 0; mi < 4; mi++)
#pragma unroll
                for (int n = 0; n < 4; n++) {
                    const int ni = n >> 1, s = n & 1;
                    mma_f16(acc[mi][n], ah[mi], bh[ni][s], bh[ni][s + 2]);
                }
        }
    }

    const int g = lane >> 2, t2 = (lane & 3) * 2, t = lane & 3;

    if (EPI == 1 || EPI == 2) {
#pragma unroll
        for (int mi = 0; mi < 4; mi++) {
            const int r0 = bm + wm * 64 + mi * 16 + g;
#pragma unroll
            for (int n = 0; n < 4; n++) {
                const int col = bn + wn * 32 + n * 8 + t2;
                const float b0 = bias[col], b1 = bias[col + 1];
#pragma unroll
                for (int h = 0; h < 2; h++) {
                    const int row = r0 + h * 8;
                    if (row >= M) continue;
                    float v0 = acc[mi][n][2 * h + 0] + b0;
                    float v1 = acc[mi][n][2 * h + 1] + b1;
                    if (EPI == 1) {
                        v0 = 0.5f * v0 * (1.f + erff(v0 * 0.70710678118654752f));
                        v1 = 0.5f * v1 * (1.f + erff(v1 * 0.70710678118654752f));
                    }
                    *(uint32_t*)(Ch + (size_t)row * N + col) = pack_h2(v0, v1);
                }
            }
        }
    } else {   // EPI == 3: fused residual + LayerNorm
        __syncthreads();
        float* sred = (float*)smem;
#pragma unroll
        for (int mi = 0; mi < 4; mi++) {
#pragma unroll
            for (int h = 0; h < 2; h++) {
                const int rl = wm * 64 + mi * 16 + g + h * 8;
                const int grow = bm + rl;
                const int gr = (grow < M) ? grow : 0;
                float ps = 0.f, pq = 0.f;
#pragma unroll
                for (int n = 0; n < 4; n++) {
                    const int col = wn * 32 + n * 8 + t2;
                    const float2 qv = *(const float2*)(resid + (size_t)gr * 256 + col);
                    const float v0 = acc[mi][n][2 * h + 0] + bias[col] + qv.x;
                    const float v1 = acc[mi][n][2 * h + 1] + bias[col + 1] + qv.y;
                    acc[mi][n][2 * h + 0] = v0;
                    acc[mi][n][2 * h + 1] = v1;
                    ps += v0 + v1;
                    pq += v0 * v0 + v1 * v1;
                }
                ps += __shfl_xor_sync(0xffffffffu, ps, 1);
                pq += __shfl_xor_sync(0xffffffffu, pq, 1);
                ps += __shfl_xor_sync(0xffffffffu, ps, 2);
                pq += __shfl_xor_sync(0xffffffffu, pq, 2);
                if (t == 0) {
                    sred[rl * 8 + wn] = ps;
                    sred[1024 + rl * 8 + wn] = pq;
                }
            }
        }
        __syncthreads();
#pragma unroll
        for (int mi = 0; mi < 4; mi++) {
#pragma unroll
            for (int h = 0; h < 2; h++) {
                const int rl = wm * 64 + mi * 16 + g + h * 8;
                const int grow = bm + rl;
                if (grow >= M) continue;
                float ts = 0.f, tq = 0.f;
#pragma unroll
                for (int i = 0; i < 8; i++) {
                    ts += sred[rl * 8 + i];
                    tq += sred[1024 + rl * 8 + i];
                }
                const float mean = ts * (1.f / 256.f);
                const float var  = fmaxf(tq * (1.f / 256.f) - mean * mean, 0.f);
                const float inv  = rsqrtf(var + 1e-5f);
#pragma unroll
                for (int n = 0; n < 4; n++) {
                    const int col = wn * 32 + n * 8 + t2;
                    const float o0 = (acc[mi][n][2 * h + 0] - mean) * inv * gamma[col]     + beta[col];
                    const float o1 = (acc[mi][n][2 * h + 1] - mean) * inv * gamma[col + 1] + beta[col + 1];
                    *(float2*)(outF + (size_t)grow * 256 + col) = make_float2(o0, o1);
                    if (Ch) *(uint32_t*)(Ch + (size_t)grow * 256 + col) = pack_h2(o0, o1);
                }
            }
        }
    }
}

// ---------------- GEMM (narrow): CTA 128x128, BK=32, 256 threads, fp32 out --
// Stores only columns < Nuse (pad columns computed but not written).
#define STAGEB2 (2*TILEA)
#define GSMEM2  (NSTG*STAGEB2)

__device__ __forceinline__ void load_stage_n(
    int stage,
    const __half* __restrict__ A, const __half* __restrict__ B,
    int bm, int bn, int M, int K, int k0, int tid, uint32_t sb)
{
#pragma unroll
    for (int i = 0; i < 4; i++) {
        const int c   = i * 256 + tid;
        const bool isA = c < 512;
        const int cc  = isA ? c : c - 512;
        const int r   = cc >> 2;
        const int kc  = cc & 3;
        const __half* src = isA ? A : B;
        int grow = (isA ? bm : bn) + r;
        int ok = 16;
        if (isA && grow >= M) { grow = 0; ok = 0; }
        const uint32_t dst = sb + stage * STAGEB2 + (isA ? 0 : TILEA) + r * ROWB + kc * 16;
        cpa16(dst, src + (size_t)grow * K + k0 + kc * 8, ok);
    }
}

__global__ __launch_bounds__(256, 1)
void mma_gemm_n(const __half* __restrict__ A, const __half* __restrict__ B,
                const float* __restrict__ bias, float* __restrict__ C,
                int M, int K, int N, int Nuse)
{
    extern __shared__ char smem[];
    const uint32_t sb = smem_u32(smem);
    const int tid = threadIdx.x, wid = tid >> 5, lane = tid & 31;
    const int bm = blockIdx.y * 128, bn = blockIdx.x * 128;
    const int wm = wid & 1, wn = wid >> 1;
    const int KT = K >> 5;

    float acc[4][4][4];
#pragma unroll
    for (int a = 0; a < 4; a++)
#pragma unroll
        for (int b = 0; b < 4; b++)
#pragma unroll
            for (int r = 0; r < 4; r++) acc[a][b][r] = 0.f;

    load_stage_n(0, A, B, bm, bn, M, K, 0,  tid, sb); cpa_commit();
    load_stage_n(1, A, B, bm, bn, M, K, 32, tid, sb); cpa_commit();
    load_stage_n(2, A, B, bm, bn, M, K, 64, tid, sb); cpa_commit();

    const int lr = lane & 15, lc = lane >> 4;

    for (int kt = 0; kt < KT; kt++) {
        cpa_wait<2>();
        __syncthreads();
        if (kt + 3 < KT)
            load_stage_n((kt + 3) % NSTG, A, B, bm, bn, M, K, (kt + 3) * 32, tid, sb);
        cpa_commit();

        const uint32_t st = sb + (kt % NSTG) * STAGEB2;
#pragma unroll
        for (int kk = 0; kk < 2; kk++) {
            const uint32_t colo = kk * 32 + lc * 16;
            uint32_t ah[4][4], bh[2][4];
#pragma unroll
            for (int mi = 0; mi < 4; mi++) {
                const uint32_t ra = (wm * 64 + mi * 16 + lr) * ROWB + colo;
                ldm_x4(ah[mi][0], ah[mi][1], ah[mi][2], ah[mi][3], st + ra);
            }
#pragma unroll
            for (int ni = 0; ni < 2; ni++) {
                const uint32_t rb = (wn * 32 + ni * 16 + lr) * ROWB + colo;
                ldm_x4(bh[ni][0], bh[ni][1], bh[ni][2], bh[ni][3], st + TILEA + rb);
            }
#pragma unroll
            for (int mi = 0; mi < 4; mi++)
#pragma unroll
                for (int n = 0; n < 4; n++) {
                    const int ni = n >> 1, s = n & 1;
                    mma_f16(acc[mi][n], ah[mi], bh[ni][s], bh[ni][s + 2]);
                }
        }
    }

    const int g = lane >> 2, t2 = (lane & 3) * 2;
#pragma unroll
    for (int mi = 0; mi < 4; mi++) {
        const int r0 = bm + wm * 64 + mi * 16 + g;
#pragma unroll
        for (int n = 0; n < 4; n++) {
            const int col = bn + wn * 32 + n * 8 + t2;
            if (col >= Nuse) continue;           // pad columns never read downstream
            const float b0 = bias[col], b1 = bias[col + 1];
#pragma unroll
            for (int h = 0; h < 2; h++) {
                const int row = r0 + h * 8;
                if (row >= M) continue;
                *(float2*)(C + (size_t)row * N + col) =
                    make_float2(acc[mi][n][2 * h + 0] + b0, acc[mi][n][2 * h + 1] + b1);
            }
        }
    }
}

// ---------------- fused prep: activations + weight transposes + bias -------
#define SEG0 65536
#define SEG1 (SEG0+49152)
#define SEG2 (SEG1+24576)
#define SEG3 (SEG2+512)
#define SEG4 (SEG3+24064)
#define SEG5 (SEG4+65536)
#define SEG6 (SEG5+262144)
#define SEG7 (SEG6+262144)
#define SEG8 (SEG7+384)

#define AQ4  (MTOT*Dm/4)
#define A34  (Bsz*10000*Dm/4)
#define A44  (Bsz*2500*Dm/4)
#define A54  (Bsz*625*Dm/4)
#define NA4  (AQ4+A34+A44+A54)

__global__ void prep_all(const float4* __restrict__ q,  const float4* __restrict__ p3,
                         const float4* __restrict__ p4, const float4* __restrict__ p5,
                         __half* __restrict__ qh, __half* __restrict__ valin,
                         const float* __restrict__ Wv,
                         const float* __restrict__ Woff, const float* __restrict__ Wattn,
                         const float* __restrict__ Wref, const float* __restrict__ Wo,
                         const float* __restrict__ W1,   const float* __restrict__ W2,
                         const float* __restrict__ boff, const float* __restrict__ battn,
                         const float* __restrict__ bref,
                         __half* __restrict__ WvT, __half* __restrict__ WqT,
                         __half* __restrict__ WoT, __half* __restrict__ W1T,
                         __half* __restrict__ W2T, float* __restrict__ bq)
{
    const int i = blockIdx.x * blockDim.x + threadIdx.x;
    if (i < NA4) {
        float4 v; __half* dst; int o;
        if (i < AQ4)                  { v = q [i];                   dst = qh;    o = i; }
        else if (i < AQ4 + A34)       { v = p3[i - AQ4];             dst = valin; o = i - AQ4; }
        else if (i < AQ4 + A34 + A44) { v = p4[i - AQ4 - A34];       dst = valin; o = i - AQ4; }
        else                          { v = p5[i - AQ4 - A34 - A44]; dst = valin; o = i - AQ4; }
        uint2 uh;
        uh.x = pack_h2(v.x, v.y);
        uh.y = pack_h2(v.z, v.w);
        *(uint2*)(dst + (size_t)o * 4) = uh;
        return;
    }
    const int w = i - NA4;
    if (w < SEG0) {
        const int n = w / Dm, k = w % Dm;
        WvT[w] = __float2half_rn(Wv[(size_t)k * Dm + n]);
    } else if (w < SEG1) {
        const int j = w - SEG0, n = j / Dm, k = j % Dm;
        WqT[j] = __float2half_rn(Woff[(size_t)k * 192 + n]);
    } else if (w < SEG2) {
        const int j = w - SEG1, n = j / Dm, k = j % Dm;
        WqT[192 * Dm + j] = __float2half_rn(Wattn[(size_t)k * 96 + n]);
    } else if (w < SEG3) {
        const int j = w - SEG2, n = j / Dm, k = j % Dm;
        WqT[288 * Dm + j] = __float2half_rn(Wref[(size_t)k * 2 + n]);
    } else if (w < SEG4) {
        WqT[290 * Dm + (w - SEG3)] = __float2half_rn(0.f);
    } else if (w < SEG5) {
        const int j = w - SEG4, n = j / Dm, k = j % Dm;
        WoT[j] = __float2half_rn(Wo[(size_t)k * Dm + n]);
    } else if (w < SEG6) {
        const int j = w - SEG5, n = j / Dm, k = j % Dm;
        W1T[j] = __float2half_rn(W1[(size_t)k * FFd + n]);
    } else if (w < SEG7) {
        const int j = w - SEG6, n = j / FFd, k = j % FFd;
        W2T[j] = __float2half_rn(W2[(size_t)k * Dm + n]);
    } else if (w < SEG8) {
        const int j = w - SEG7;
        bq[j] = (j < 192) ? boff[j] : (j < 288) ? battn[j - 192] : (j < 290) ? bref[j - 288] : 0.f;
    }
}

// ---------------- fused softmax + sigmoid + bilinear sampling ----------------
// 32 threads/token, 4 tokens per 128-thread block; thread = (head, 8-ch group).
// Per-point recompute; half2 accumulation held across the 4 points of each
// level, finalized to fp32 once per level.   (R14 structure — proven optimum)
__global__ __launch_bounds__(128)
void sample_kernel(__half* __restrict__ oh)
{
    const int tid  = threadIdx.x;
    const int sub  = tid >> 5;
    const int t    = blockIdx.x * 4 + sub;
    const int b    = t / NTOK;
    const int tid2 = tid & 31;
    const int h    = tid2 >> 2;
    const int cg   = tid2 & 3;

    __shared__ float s_aw[4][96], s_x[4][96], s_y[4][96];

    const float refx = 1.f / (1.f + __expf(-g_qcat[(size_t)t * NQC + 288]));
    const float refy = 1.f / (1.f + __expf(-g_qcat[(size_t)t * NQC + 289]));

    for (int i = tid2; i < 96; i += 32) {
        const int lp = i % 12;
        const int l  = lp >> 2;
        const float ox = g_qcat[(size_t)t * NQC + i * 2 + 0];
        const float oy = g_qcat[(size_t)t * NQC + i * 2 + 1];
        s_x[sub][i]  = fmaf(refx, (float)c_lvlW[l], ox) - 0.5f;
        s_y[sub][i]  = fmaf(refy, (float)c_lvlH[l], oy) - 0.5f;
        s_aw[sub][i] = g_qcat[(size_t)t * NQC + 192 + i];
    }
    __syncthreads();

    if (tid2 < 8) {
        float m = -1e30f;
#pragma unroll
        for (int j = 0; j < 12; j++) m = fmaxf(m, s_aw[sub][tid2 * 12 + j]);
        float s = 0.f;
#pragma unroll
        for (int j = 0; j < 12; j++) {
            const float e = __expf(s_aw[sub][tid2 * 12 + j] - m);
            s_aw[sub][tid2 * 12 + j] = e; s += e;
        }
        const float inv = 1.f / s;
#pragma unroll
        for (int j = 0; j < 12; j++) s_aw[sub][tid2 * 12 + j] *= inv;
    }
    __syncthreads();

    float acc[8];
#pragma unroll
    for (int i = 0; i < 8; i++) acc[i] = 0.f;

#pragma unroll
    for (int l = 0; l < 3; l++) {
        const int Hl = c_lvlH[l], Wl = c_lvlW[l];
        const __half* vl = g_valh + c_lvlOff[l] + (size_t)b * c_lvlN[l] * Dm + (h * DHd + cg * 8);

        __half2 pa0 = __float2half2_rn(0.f), pa1 = pa0, pa2 = pa0, pa3 = pa0;
#pragma unroll
        for (int p = 0; p < 4; p++) {
            const int idx = h * 12 + l * 4 + p;
            const float x = s_x[sub][idx], y = s_y[sub][idx], w = s_aw[sub][idx];
            const float x0f = floorf(x), y0f = floorf(y);
            const int x0 = (int)x0f, y0 = (int)y0f;
            const float lx = x - x0f, ly = y - y0f;
            const float w00 = w * (1.f - lx) * (1.f - ly);
            const float w01 = w * lx * (1.f - ly);
            const float w10 = w * (1.f - lx) * ly;
            const float w11 = w * lx * ly;
            const bool xin0 = (x0 >= 0) & (x0 < Wl);
            const bool xin1 = (x0 + 1 >= 0) & (x0 + 1 < Wl);
            const bool yin0 = (y0 >= 0) & (y0 < Hl);
            const bool yin1 = (y0 + 1 >= 0) & (y0 + 1 < Hl);
#define ACC8(cond, wgt, ro, co) \
            if (cond) { \
                const __half2 wh = __float2half2_rn(wgt); \
                const uint4 u = *(const uint4*)(vl + (size_t)((ro) * Wl + (co)) * Dm); \
                const __half2* hp = (const __half2*)&u; \
                pa0 = __hfma2(hp[0], wh, pa0); \
                pa1 = __hfma2(hp[1], wh, pa1); \
                pa2 = __hfma2(hp[2], wh, pa2); \
                pa3 = __hfma2(hp[3], wh, pa3); \
            }
            ACC8(xin0 & yin0, w00, y0,     x0)
            ACC8(xin1 & yin0, w01, y0,     x0 + 1)
            ACC8(xin0 & yin1, w10, y0 + 1, x0)
            ACC8(xin1 & yin1, w11, y0 + 1, x0 + 1)
#undef ACC8
        }
        const float2 f0 = __half22float2(pa0);
        const float2 f1 = __half22float2(pa1);
        const float2 f2 = __half22float2(pa2);
        const float2 f3 = __half22float2(pa3);
        acc[0] += f0.x; acc[1] += f0.y;
        acc[2] += f1.x; acc[3] += f1.y;
        acc[4] += f2.x; acc[5] += f2.y;
        acc[6] += f3.x; acc[7] += f3.y;
    }
    uint4 o;
    o.x = pack_h2(acc[0], acc[1]);
    o.y = pack_h2(acc[2], acc[3]);
    o.z = pack_h2(acc[4], acc[5]);
    o.w = pack_h2(acc[6], acc[7]);
    *(uint4*)(oh + (size_t)t * Dm + h * DHd + cg * 8) = o;
}

// ---------------- host orchestration ----------------
extern "C" void kernel_launch(void* const* d_in, const int* in_sizes, int n_in,
                              void* d_out, int out_size)
{
    const float* query = (const float*)d_in[0];
    const float* p3    = (const float*)d_in[1];
    const float* p4    = (const float*)d_in[2];
    const float* p5    = (const float*)d_in[3];
    const float* Wv    = (const float*)d_in[4];
    const float* bv    = (const float*)d_in[5];
    const float* Woff  = (const float*)d_in[6];
    const float* boff  = (const float*)d_in[7];
    const float* Wattn = (const float*)d_in[8];
    const float* battn = (const float*)d_in[9];
    const float* Wref  = (const float*)d_in[10];
    const float* bref  = (const float*)d_in[11];
    const float* Wo    = (const float*)d_in[12];
    const float* bo    = (const float*)d_in[13];
    const float* W1    = (const float*)d_in[14];
    const float* b1    = (const float*)d_in[15];
    const float* W2    = (const float*)d_in[16];
    const float* b2    = (const float*)d_in[17];
    const float* g1    = (const float*)d_in[18];
    const float* be1   = (const float*)d_in[19];
    const float* g2    = (const float*)d_in[20];
    const float* be2   = (const float*)d_in[21];
    float* out = (float*)d_out;

    cudaFuncSetAttribute(mma_gemm<1>, cudaFuncAttributeMaxDynamicSharedMemorySize, GSMEM);
    cudaFuncSetAttribute(mma_gemm<2>, cudaFuncAttributeMaxDynamicSharedMemorySize, GSMEM);
    cudaFuncSetAttribute(mma_gemm<3>, cudaFuncAttributeMaxDynamicSharedMemorySize, GSMEM);
    cudaFuncSetAttribute(mma_gemm_n,  cudaFuncAttributeMaxDynamicSharedMemorySize, GSMEM2);

#define SYM(T, p, s) T* p; cudaGetSymbolAddress((void**)&p, s)
    SYM(__half, valin, g_valin);
    SYM(__half, valh, g_valh);
    SYM(__half, qh, g_qh);
    SYM(float, qcat, g_qcat);
    SYM(__half, sah, g_sah);
    SYM(float, qf, g_q);
    SYM(__half, qnh, g_qnh);
    SYM(__half, h1h, g_h1h);
    SYM(__half, WvT, g_WvT); SYM(__half, WqT, g_WqT);
    SYM(__half, WoT, g_WoT); SYM(__half, W1T, g_W1T); SYM(__half, W2T, g_W2T);
    SYM(float, bq, g_bq);
#undef SYM

    // ---- fused prep (1 launch) ----
    prep_all<<<(NA4 + SEG8 + 255) / 256, 256>>>(
        (const float4*)query, (const float4*)p3, (const float4*)p4, (const float4*)p5,
        qh, valin,
        Wv, Woff, Wattn, Wref, Wo, W1, W2, boff, battn, bref,
        WvT, WqT, WoT, W1T, W2T, bq);

    const int TM = (MTOT + 127) / 128;   // 411

    // ---- value projection (fp16 out) ----
    mma_gemm<2><<<dim3(1, TM), 512, GSMEM>>>(valin, WvT, bv, nullptr, valh,
                                             nullptr, nullptr, nullptr, MTOT, Dm, Dm);
    // ---- fused q projections (off|attn|ref, N=384, stores cols < 290) ----
    mma_gemm_n<<<dim3(3, TM), 256, GSMEM2>>>(qh, WqT, bq, qcat, MTOT, Dm, NQC, NQUSE);
    // ---- sampling ----
    sample_kernel<<<MTOT / 4, 128>>>(sah);
    // ---- output projection + residual + LN1 (fused) ----
    mma_gemm<3><<<dim3(1, TM), 512, GSMEM>>>(sah, WoT, bo, qf, qnh,
                                             query, g1, be1, MTOT, Dm, Dm);
    // ---- FFN ----
    mma_gemm<1><<<dim3(4, TM), 512, GSMEM>>>(qnh, W1T, b1, nullptr, h1h,
                                             nullptr, nullptr, nullptr, MTOT, Dm, FFd);
    mma_gemm<3><<<dim3(1, TM), 512, GSMEM>>>(h1h, W2T, b2, out, nullptr,
                                             qf, g2, be2, MTOT, FFd, Dm);
}